// round 3
// baseline (speedup 1.0000x reference)
#include <cuda_runtime.h>
#include <cstdint>

#define B 32
#define F 1024
#define S 2048
#define KK 16
#define NSPLIT 16
#define RPS (S / NSPLIT)   // 128 rows per split

// Scratch (allocation-free rule: __device__ globals)
__device__ float g_partial[B * NSPLIT * S];   // 4 MB partial column sums

// ---------------------------------------------------------------------------
// Kernel 1: partial column sums of w[B, S, S] over a 128-row slice.
// 2048 blocks x 128 threads (~55 warps/SM). __ldcs streaming loads (touch-once
// data, keep L2 clean), dual accumulators -> 8 independent 16B loads in flight.
// ---------------------------------------------------------------------------
__global__ void colsum_partial_kernel(const float* __restrict__ w) {
    const int c4    = blockIdx.x * blockDim.x + threadIdx.x;  // float4 col group
    const int split = blockIdx.y;
    const int b     = blockIdx.z;

    const float4* p = reinterpret_cast<const float4*>(w)
                    + (size_t)b * S * (S / 4)
                    + (size_t)(split * RPS) * (S / 4) + c4;

    float4 a0 = make_float4(0.f, 0.f, 0.f, 0.f);
    float4 a1 = make_float4(0.f, 0.f, 0.f, 0.f);
#pragma unroll 4
    for (int r = 0; r < RPS; r += 2) {
        float4 v0 = __ldcs(p);
        float4 v1 = __ldcs(p + (S / 4));
        a0.x += v0.x; a0.y += v0.y; a0.z += v0.z; a0.w += v0.w;
        a1.x += v1.x; a1.y += v1.y; a1.z += v1.z; a1.w += v1.w;
        p += 2 * (S / 4);
    }
    float4 acc = make_float4(a0.x + a1.x, a0.y + a1.y, a0.z + a1.z, a0.w + a1.w);

    float4* outp = reinterpret_cast<float4*>(g_partial)
                 + (size_t)(b * NSPLIT + split) * (S / 4) + c4;
    *outp = acc;
}

// ---------------------------------------------------------------------------
// Kernel 2 (fused): per-batch fold of partials + 16-round packed argmax top-k
// + feature-column gather. One block per batch, 1024 threads.
// Key = (monotone float bits << 32) | (S-1-col): max key = largest value,
// ties broken toward the LOWEST column index (matches lax.top_k).
// ---------------------------------------------------------------------------
__global__ void topk_gather_kernel(const float* __restrict__ x,
                                   float* __restrict__ out) {
    __shared__ unsigned long long skey[S];
    __shared__ unsigned long long warpmax[32];
    __shared__ int scol[KK];

    const int b = blockIdx.x;
    const int t = threadIdx.x;          // 0..1023
    const int lane = t & 31;
    const int wid  = t >> 5;            // 0..31

    // Fold 16 partials -> packed sort keys in smem (2 columns per thread)
#pragma unroll
    for (int j = 0; j < S / 1024; ++j) {
        const int c = t + j * 1024;
        float s = 0.f;
#pragma unroll
        for (int p = 0; p < NSPLIT; ++p)
            s += g_partial[(size_t)(b * NSPLIT + p) * S + c];
        unsigned int bits = __float_as_uint(s);
        bits = (bits & 0x80000000u) ? ~bits : (bits | 0x80000000u);
        skey[c] = ((unsigned long long)bits << 32)
                | (unsigned int)(S - 1 - c);
    }
    __syncthreads();

    // 16 argmax rounds, shuffle-based reduction (2 barriers per round)
    for (int k = 0; k < KK; ++k) {
        unsigned long long best = skey[t];
        unsigned long long v2   = skey[t + 1024];
        if (v2 > best) best = v2;
#pragma unroll
        for (int off = 16; off > 0; off >>= 1) {
            unsigned long long o = __shfl_down_sync(0xffffffffu, best, off);
            if (o > best) best = o;
        }
        if (lane == 0) warpmax[wid] = best;
        __syncthreads();
        if (wid == 0) {
            unsigned long long m = warpmax[lane];
#pragma unroll
            for (int off = 16; off > 0; off >>= 1) {
                unsigned long long o = __shfl_down_sync(0xffffffffu, m, off);
                if (o > m) m = o;
            }
            if (lane == 0) {
                const int col = S - 1 - (int)(m & 0xFFFFFFFFu);
                scol[k] = col;
                skey[col] = 0ull;      // mask the winner
            }
        }
        __syncthreads();
    }

    // Gather: out[b,f,k] = x[b,f,scol[k]]. Coalesced writes; 16 independent
    // scattered reads per thread for MLP.
    const float* xb = x + (size_t)b * F * S;
    float*       ob = out + (size_t)b * F * KK;
#pragma unroll
    for (int j = 0; j < (F * KK) / 1024; ++j) {   // 16 iters
        const int i = t + j * 1024;
        const int k = i & (KK - 1);
        const int f = i >> 4;
        ob[i] = __ldg(xb + (size_t)f * S + scol[k]);
    }
}

// ---------------------------------------------------------------------------
extern "C" void kernel_launch(void* const* d_in, const int* in_sizes, int n_in,
                              void* d_out, int out_size) {
    const float* x = (const float*)d_in[0];  // [B, F, S]
    const float* w = (const float*)d_in[1];  // [B, S, S]
    float* out = (float*)d_out;              // [B, F, K]

    dim3 g1(S / (128 * 4), NSPLIT, B);       // (4, 16, 32) = 2048 blocks
    colsum_partial_kernel<<<g1, 128>>>(w);

    topk_gather_kernel<<<B, 1024>>>(x, out);
}

// round 7
// speedup vs baseline: 1.1232x; 1.1232x over previous
#include <cuda_runtime.h>
#include <cstdint>

#define B 32
#define F 1024
#define S 2048
#define KK 16
#define NSPLIT 8
#define RPS (S / NSPLIT)   // 256 rows per split

// Scratch (allocation-free rule: __device__ globals)
__device__ float g_partial[B * NSPLIT * S];   // 2 MB partial column sums
__device__ int   g_idx[B * KK];               // top-k indices per batch

// ---------------------------------------------------------------------------
// Kernel 1: partial column sums of w[B, S, S] over a 256-row slice.
// EXACT R1 config (measured 81.7us, DRAM 83.7%): float4 __ldg, unroll 8,
// 1024 blocks x 128 threads.
// ---------------------------------------------------------------------------
__global__ void colsum_partial_kernel(const float* __restrict__ w) {
    const int c4    = blockIdx.x * blockDim.x + threadIdx.x;  // float4 col group
    const int split = blockIdx.y;
    const int b     = blockIdx.z;

    const float4* wp = reinterpret_cast<const float4*>(w + (size_t)b * S * S);
    const float4* p  = wp + (size_t)(split * RPS) * (S / 4) + c4;

    float4 acc = make_float4(0.f, 0.f, 0.f, 0.f);
#pragma unroll 8
    for (int r = 0; r < RPS; ++r) {
        float4 v = __ldg(p);
        acc.x += v.x; acc.y += v.y; acc.z += v.z; acc.w += v.w;
        p += S / 4;
    }

    float4* outp = reinterpret_cast<float4*>(g_partial)
                 + (size_t)(b * NSPLIT + split) * (S / 4) + c4;
    *outp = acc;
}

// ---------------------------------------------------------------------------
// Kernel 2: per-batch fold of 8 partials + 16-round packed argmax top-k.
// One block per batch, 512 threads, shuffle-based reduction (2 barriers/round).
// Key = (monotone float bits << 32) | (S-1-col): max key = largest value,
// ties broken toward the LOWEST column index (matches lax.top_k).
// ---------------------------------------------------------------------------
__global__ void topk_kernel() {
    __shared__ unsigned long long skey[S];
    __shared__ unsigned long long warpmax[16];

    const int b = blockIdx.x;
    const int t = threadIdx.x;          // 0..511
    const int lane = t & 31;
    const int wid  = t >> 5;            // 0..15

    // Fold 8 partials -> packed sort keys in smem (4 columns per thread)
#pragma unroll
    for (int j = 0; j < S / 512; ++j) {
        const int c = t + j * 512;
        float s = 0.f;
#pragma unroll
        for (int p = 0; p < NSPLIT; ++p)
            s += g_partial[(size_t)(b * NSPLIT + p) * S + c];
        unsigned int bits = __float_as_uint(s);
        bits = (bits & 0x80000000u) ? ~bits : (bits | 0x80000000u);
        skey[c] = ((unsigned long long)bits << 32)
                | (unsigned int)(S - 1 - c);
    }
    __syncthreads();

    for (int k = 0; k < KK; ++k) {
        unsigned long long best = 0ull;
#pragma unroll
        for (int j = 0; j < S / 512; ++j) {
            unsigned long long v = skey[t + j * 512];
            if (v > best) best = v;
        }
#pragma unroll
        for (int off = 16; off > 0; off >>= 1) {
            unsigned long long o = __shfl_down_sync(0xffffffffu, best, off);
            if (o > best) best = o;
        }
        if (lane == 0) warpmax[wid] = best;
        __syncthreads();
        if (wid == 0) {
            unsigned long long m = (lane < 16) ? warpmax[lane] : 0ull;
#pragma unroll
            for (int off = 8; off > 0; off >>= 1) {
                unsigned long long o = __shfl_down_sync(0xffffffffu, m, off);
                if (o > m) m = o;
            }
            if (lane == 0) {
                const int col = S - 1 - (int)(m & 0xFFFFFFFFu);
                g_idx[b * KK + k] = col;
                skey[col] = 0ull;      // mask the winner
            }
        }
        __syncthreads();
    }
}

// ---------------------------------------------------------------------------
// Kernel 3: gather out[b,f,k] = x[b,f,idx[b,k]]. 2048 blocks -> full chip.
// Coalesced 64B writes per (b,f) row; scattered 4B reads are L2/DRAM-friendly
// (16 MB total with sector amplification).
// ---------------------------------------------------------------------------
__global__ void gather_kernel(const float* __restrict__ x,
                              float* __restrict__ out) {
    const int i = blockIdx.x * blockDim.x + threadIdx.x;
    if (i >= B * F * KK) return;
    const int k = i & (KK - 1);
    const int f = (i >> 4) & (F - 1);
    const int b = i >> 14;
    const int col = g_idx[b * KK + k];
    out[i] = __ldg(x + (size_t)b * F * S + (size_t)f * S + col);
}

// ---------------------------------------------------------------------------
extern "C" void kernel_launch(void* const* d_in, const int* in_sizes, int n_in,
                              void* d_out, int out_size) {
    const float* x = (const float*)d_in[0];  // [B, F, S]
    const float* w = (const float*)d_in[1];  // [B, S, S]
    float* out = (float*)d_out;              // [B, F, K]

    dim3 g1(S / (128 * 4), NSPLIT, B);       // (4, 8, 32) = 1024 blocks
    colsum_partial_kernel<<<g1, 128>>>(w);

    topk_kernel<<<B, 512>>>();

    const int total = B * F * KK;            // 524288
    gather_kernel<<<total / 256, 256>>>(x, out);
}

// round 9
// speedup vs baseline: 1.1253x; 1.0019x over previous
#include <cuda_runtime.h>
#include <cstdint>

#define B 32
#define F 1024
#define S 2048
#define KK 16
#define NSPLIT 8
#define RPS (S / NSPLIT)   // 256 rows per split

// Scratch (allocation-free rule: __device__ globals)
__device__ float g_partial[B * NSPLIT * S];   // 2 MB partial column sums
__device__ int   g_idx[B * KK];               // top-k indices per batch

static __device__ __forceinline__ unsigned long long u64max(
    unsigned long long a, unsigned long long b) { return a > b ? a : b; }

// ---------------------------------------------------------------------------
// Kernel 1: partial column sums of w[B, S, S] over a 256-row slice.
// EXACT measured-best config (81.8us, DRAM 83.5%): float4 __ldg, unroll 8,
// 1024 blocks x 128 threads. DO NOT TOUCH.
// ---------------------------------------------------------------------------
__global__ void colsum_partial_kernel(const float* __restrict__ w) {
    const int c4    = blockIdx.x * blockDim.x + threadIdx.x;  // float4 col group
    const int split = blockIdx.y;
    const int b     = blockIdx.z;

    const float4* wp = reinterpret_cast<const float4*>(w + (size_t)b * S * S);
    const float4* p  = wp + (size_t)(split * RPS) * (S / 4) + c4;

    float4 acc = make_float4(0.f, 0.f, 0.f, 0.f);
#pragma unroll 8
    for (int r = 0; r < RPS; ++r) {
        float4 v = __ldg(p);
        acc.x += v.x; acc.y += v.y; acc.z += v.z; acc.w += v.w;
        p += S / 4;
    }

    float4* outp = reinterpret_cast<float4*>(g_partial)
                 + (size_t)(b * NSPLIT + split) * (S / 4) + c4;
    *outp = acc;
}

// ---------------------------------------------------------------------------
// Kernel 2: per-batch fold + top-16 via single-warp group-max tournament.
// One block per batch, 512 threads.
//   Fold: thread t sums partials for cols 4t..4t+3 (float4 loads, L2-hot),
//         builds packed keys in smem, and half-warp shuffle-reduces a max for
//         its 64-column group -> 32 group maxes.
//   Select (warp 0 only, NO block barriers): 32 group maxes in registers,
//         16 rounds of {5-shfl argmax; zero winner key; 32-lane rescan of the
//         winner's 64-entry group; 5-shfl reduce; update 1 register}.
// Key = (monotone float bits << 32) | (S-1-col): max key = largest value,
// ties broken toward the LOWEST column index (matches lax.top_k).
// ---------------------------------------------------------------------------
__global__ void topk_kernel() {
    __shared__ unsigned long long skey[S];
    __shared__ unsigned long long groupmax[32];

    const int b = blockIdx.x;
    const int t = threadIdx.x;          // 0..511
    const int lane = t & 31;

    // ---- Fold: cols 4t..4t+3, one float4 per partial slice ----
    float4 s = make_float4(0.f, 0.f, 0.f, 0.f);
#pragma unroll
    for (int p = 0; p < NSPLIT; ++p) {
        float4 v = *(reinterpret_cast<const float4*>(g_partial)
                     + (size_t)(b * NSPLIT + p) * (S / 4) + t);
        s.x += v.x; s.y += v.y; s.z += v.z; s.w += v.w;
    }

    unsigned long long kmax = 0ull;
    const float sv[4] = {s.x, s.y, s.z, s.w};
#pragma unroll
    for (int j = 0; j < 4; ++j) {
        const int c = 4 * t + j;
        unsigned int bits = __float_as_uint(sv[j]);
        bits = (bits & 0x80000000u) ? ~bits : (bits | 0x80000000u);
        unsigned long long key = ((unsigned long long)bits << 32)
                               | (unsigned int)(S - 1 - c);
        skey[c] = key;
        kmax = u64max(kmax, key);
    }

    // Half-warp reduce: lanes 0-15 cover one 64-col group, 16-31 the next.
#pragma unroll
    for (int off = 8; off > 0; off >>= 1)
        kmax = u64max(kmax, __shfl_down_sync(0xffffffffu, kmax, off, 16));
    if ((lane & 15) == 0) {
        const int g = (4 * t) >> 6;               // group of this half-warp
        groupmax[g] = kmax;
    }
    __syncthreads();

    // ---- Selection: warp 0 only ----
    if (t < 32) {
        unsigned long long gm = groupmax[lane];   // lane l owns group l

        for (int k = 0; k < KK; ++k) {
            // global argmax over 32 group maxes
            unsigned long long m = gm;
#pragma unroll
            for (int off = 16; off > 0; off >>= 1)
                m = u64max(m, __shfl_down_sync(0xffffffffu, m, off));
            m = __shfl_sync(0xffffffffu, m, 0);

            const int col = S - 1 - (int)(m & 0xFFFFFFFFu);
            if (lane == 0) {
                g_idx[b * KK + k] = col;
                skey[col] = 0ull;                 // mask the winner
            }
            __syncwarp();

            // rescan the winner's group (64 entries, 2 per lane)
            const int g = col >> 6;
            unsigned long long a0 = skey[(g << 6) + lane];
            unsigned long long a1 = skey[(g << 6) + 32 + lane];
            unsigned long long mm = u64max(a0, a1);
#pragma unroll
            for (int off = 16; off > 0; off >>= 1)
                mm = u64max(mm, __shfl_down_sync(0xffffffffu, mm, off));
            mm = __shfl_sync(0xffffffffu, mm, 0);
            if (lane == g) gm = mm;
        }
    }
}

// ---------------------------------------------------------------------------
// Kernel 3: gather out[b,f,k] = x[b,f,idx[b,k]]. 2048 blocks -> full chip.
// Coalesced 64B writes per (b,f) row; scattered 4B reads are L2/DRAM-friendly.
// ---------------------------------------------------------------------------
__global__ void gather_kernel(const float* __restrict__ x,
                              float* __restrict__ out) {
    const int i = blockIdx.x * blockDim.x + threadIdx.x;
    if (i >= B * F * KK) return;
    const int k = i & (KK - 1);
    const int f = (i >> 4) & (F - 1);
    const int b = i >> 14;
    const int col = g_idx[b * KK + k];
    out[i] = __ldg(x + (size_t)b * F * S + (size_t)f * S + col);
}

// ---------------------------------------------------------------------------
extern "C" void kernel_launch(void* const* d_in, const int* in_sizes, int n_in,
                              void* d_out, int out_size) {
    const float* x = (const float*)d_in[0];  // [B, F, S]
    const float* w = (const float*)d_in[1];  // [B, S, S]
    float* out = (float*)d_out;              // [B, F, K]

    dim3 g1(S / (128 * 4), NSPLIT, B);       // (4, 8, 32) = 1024 blocks
    colsum_partial_kernel<<<g1, 128>>>(w);

    topk_kernel<<<B, 512>>>();

    const int total = B * F * KK;            // 524288
    gather_kernel<<<total / 256, 256>>>(x, out);
}